// round 4
// baseline (speedup 1.0000x reference)
#include <cuda_runtime.h>
#include <cuda_bf16.h>
#include <math.h>

#define B    32
#define NP   100
#define F_IN 36
#define FC   40
#define KNN  11
#define GDIM (KNN*FC)     // 440
#define H    3600
#define NLAY 5
#define EPSB 0.001f
#define KT   32

typedef unsigned long long u64;

// ---------------- device scratch (globals: allowed) ----------------
__device__ float d_xfeat[B*NP*FC];
__device__ float d_g[B*GDIM];
__device__ float d_hA[B*H];
__device__ float d_hB[B*H];
__device__ float d_c2[B*2];

// ---------------- packed f32x2 helpers ----------------
__device__ __forceinline__ u64 mul2(u64 a, u64 b) {
    u64 d; asm("mul.rn.f32x2 %0,%1,%2;" : "=l"(d) : "l"(a), "l"(b)); return d;
}
__device__ __forceinline__ u64 add2(u64 a, u64 b) {
    u64 d; asm("add.rn.f32x2 %0,%1,%2;" : "=l"(d) : "l"(a), "l"(b)); return d;
}
__device__ __forceinline__ u64 fma2v(u64 a, u64 b, u64 c) {
    u64 d; asm("fma.rn.f32x2 %0,%1,%2,%3;" : "=l"(d) : "l"(a), "l"(b), "l"(c)); return d;
}
__device__ __forceinline__ void unpack2(u64 v, float &lo, float &hi) {
    asm("mov.b64 {%0,%1}, %2;" : "=f"(lo), "=f"(hi) : "l"(v));
}
#define SGN2 0x8000000080000000ull
#define KM1  0xBF800000BF800000ull   /* packed (-1.0f, -1.0f) */

// Compensated accumulate: (s,c) += a*w  with exact product (TwoProd+Kahan)
__device__ __forceinline__ void kdot2(u64 &s, u64 &c, u64 a, u64 w) {
    u64 p  = mul2(a, w);
    u64 ep = fma2v(a, w, p ^ SGN2);   // exact product low part
    u64 y  = fma2v(c, KM1, p);        // p - c
    u64 t  = add2(s, y);
    u64 z  = fma2v(s, KM1, t);        // t - s
    c = fma2v(y, KM1, z);             // (t-s) - y
    c = fma2v(ep, KM1, c);            // fold product error
    s = t;
}

// ---------------- prep: build features + init c2 (bit-exact elementwise) ----
__global__ void prep_kernel(const float* __restrict__ xx,
                            const float* __restrict__ emb1,
                            const float* __restrict__ emb2,
                            const float* __restrict__ emb3,
                            const float* __restrict__ mean,
                            const float* __restrict__ stdv,
                            const float* __restrict__ vmin,
                            const float* __restrict__ vmax) {
    int idx = blockIdx.x*blockDim.x + threadIdx.x;
    if (idx >= B*NP) return;
    int b = idx / NP, p = idx % NP;
    const float* row = xx + (size_t)(b*NP + p)*F_IN;
    float* orow = d_xfeat + (size_t)(b*NP + p)*FC;
    int i1 = (int)fabsf(row[0]);
    int i2 = (int)fabsf(row[1]);
    int i3 = (int)fabsf(row[2]);
    orow[0] = emb1[i1*2+0]; orow[1] = emb1[i1*2+1];
    orow[2] = emb2[i2*2+0]; orow[3] = emb2[i2*2+1];
    orow[4] = emb3[i3*2+0]; orow[5] = emb3[i3*2+1];
    for (int f = 2; f < F_IN; f++) {
        float v = row[f];
        if (f >= 3) {
            float y = __fdiv_rn(__fsub_rn(v, mean[f]), stdv[f]);
            y = fminf(fmaxf(y, -5.0f), 5.0f);
            float sc = __fdiv_rn(2.0f, __fsub_rn(vmax[f], vmin[f]));
            float y2 = __fsub_rn(__fmul_rn(sc, __fsub_rn(y, vmin[f])), 1.0f);
            y2 = fminf(fmaxf(y2, -1.0f), 1.0f);
            v = y2;
        }
        orow[6 + (f - 2)] = v;
    }
    if (p == 0) {
        d_c2[b*2+0] = orow[12];   // ETA_C
        d_c2[b*2+1] = orow[13];   // PHI_C
    }
}

// ---------------- knn: c2 = h@Wc + bc (compensated dot), dist, top-11 -------
__global__ void knn_kernel(const float* __restrict__ Wc,
                           const float* __restrict__ bc,
                           int compute_c2) {
    int b = blockIdx.x;
    int tid = threadIdx.x;   // 128 threads
    __shared__ float s_ref[2];
    __shared__ float s_d[NP];
    __shared__ int   s_idx[KNN];

    if (compute_c2) {
        if (tid < 2) {
            const float* hrow = d_hA + (size_t)b*H;
            float s = 0.f, c = 0.f;
            #pragma unroll 4
            for (int k = 0; k < H; k++) {
                float a = hrow[k], w = Wc[k*2+tid];
                float p  = __fmul_rn(a, w);
                float ep = __fmaf_rn(a, w, -p);
                float y  = __fsub_rn(p, c);
                float t  = __fadd_rn(s, y);
                c = __fsub_rn(__fsub_rn(t, s), y);
                c = __fsub_rn(c, ep);
                s = t;
            }
            s = __fsub_rn(s, c);
            s_ref[tid] = __fadd_rn(s, bc[tid]);
        }
    } else {
        if (tid < 2) s_ref[tid] = d_c2[b*2+tid];
    }
    __syncthreads();

    if (tid < NP) {
        float dx = __fsub_rn(d_xfeat[(size_t)(b*NP + tid)*FC + 12], s_ref[0]);
        float dy = __fsub_rn(d_xfeat[(size_t)(b*NP + tid)*FC + 13], s_ref[1]);
        s_d[tid] = __fsqrt_rn(__fadd_rn(__fmul_rn(dx,dx), __fmul_rn(dy,dy)));
    }
    __syncthreads();
    if (tid < NP) {
        float mine = s_d[tid];
        int rank = 0;
        #pragma unroll 4
        for (int j = 0; j < NP; j++) {
            float dj = s_d[j];
            rank += (dj < mine) || (dj == mine && j < tid);  // stable tie-break
        }
        if (rank < KNN) s_idx[rank] = tid;
    }
    __syncthreads();
    for (int i = tid; i < GDIM; i += 128) {
        int k = i / FC, f = i - k*FC;
        d_g[(size_t)b*GDIM + i] = d_xfeat[(size_t)(b*NP + s_idx[k])*FC + f];
    }
}

// ---------------- fused GEMM (compensated fp32) + BN + ReLU -----------------
// out[32,H] = relu( bn( A[32,Kd] @ W[Kd,H] + bias ) )
__global__ void layer_kernel(const float* __restrict__ A, int Kd,
                             const float* __restrict__ W,
                             const float* __restrict__ bias,
                             const float* __restrict__ gamma,
                             const float* __restrict__ beta,
                             const float* __restrict__ mmean,
                             const float* __restrict__ mvar,
                             float* __restrict__ out) {
    __shared__ __align__(16) float2 sA[KT][34];   // [k][m] duplicated pairs, padded
    int tid = threadIdx.x;
    int n0  = blockIdx.x * 32;
    int cp  = tid & 15;
    int rq  = tid >> 4;          // 0..15
    int m0  = 2*rq;
    int n   = n0 + 2*cp;
    bool nvalid = (n < H);
    int n_safe  = nvalid ? n : n0;

    const u64* wbase = reinterpret_cast<const u64*>(W + n_safe);
    const int wstride = H/2;   // in u64 units per k-row

    u64 acc0 = 0ull, acc1 = 0ull;   // sums
    u64 cmp0 = 0ull, cmp1 = 0ull;   // compensations

    int nfull = Kd / KT;
    for (int c = 0; c < nfull; c++) {
        int k0 = c * KT;
        #pragma unroll
        for (int j = 0; j < (KT*32)/256; j++) {
            int idx = tid + j*256;
            int kk = idx & 31, m = idx >> 5;
            float v = A[(size_t)m*Kd + k0 + kk];
            sA[kk][m] = make_float2(v, v);
        }
        __syncthreads();
        #pragma unroll 4
        for (int kk = 0; kk < KT; kk++) {
            u64 w2 = wbase[(size_t)(k0+kk)*wstride];
            ulonglong2 a = *reinterpret_cast<const ulonglong2*>(&sA[kk][m0]);
            kdot2(acc0, cmp0, a.x, w2);
            kdot2(acc1, cmp1, a.y, w2);
        }
        __syncthreads();
    }
    int rem = Kd - nfull*KT;
    if (rem) {
        int k0 = nfull*KT;
        #pragma unroll
        for (int j = 0; j < (KT*32)/256; j++) {
            int idx = tid + j*256;
            int kk = idx & 31, m = idx >> 5;
            float v = (k0 + kk < Kd) ? A[(size_t)m*Kd + k0 + kk] : 0.f;
            sA[kk][m] = make_float2(v, v);
        }
        __syncthreads();
        for (int kk = 0; kk < rem; kk++) {
            u64 w2 = wbase[(size_t)(k0+kk)*wstride];
            ulonglong2 a = *reinterpret_cast<const ulonglong2*>(&sA[kk][m0]);
            kdot2(acc0, cmp0, a.x, w2);
            kdot2(acc1, cmp1, a.y, w2);
        }
        __syncthreads();
    }
    // apply pending compensation: s -= c
    acc0 = fma2v(cmp0, KM1, acc0);
    acc1 = fma2v(cmp1, KM1, acc1);

    if (nvalid) {
        float g0 = gamma[n],  g1 = gamma[n+1];
        float be0 = beta[n],  be1 = beta[n+1];
        float mm0 = mmean[n], mm1 = mmean[n+1];
        float r0 = __fdiv_rn(1.0f, __fsqrt_rn(__fadd_rn(mvar[n],   EPSB)));
        float r1 = __fdiv_rn(1.0f, __fsqrt_rn(__fadd_rn(mvar[n+1], EPSB)));
        float bi0 = bias[n], bi1 = bias[n+1];
        float a0lo, a0hi, a1lo, a1hi;
        unpack2(acc0, a0lo, a0hi);
        unpack2(acc1, a1lo, a1hi);
        float h00 = __fadd_rn(a0lo, bi0), h01 = __fadd_rn(a0hi, bi1);
        float h10 = __fadd_rn(a1lo, bi0), h11 = __fadd_rn(a1hi, bi1);
        float o00 = __fadd_rn(__fmul_rn(__fmul_rn(g0, __fsub_rn(h00, mm0)), r0), be0);
        float o01 = __fadd_rn(__fmul_rn(__fmul_rn(g1, __fsub_rn(h01, mm1)), r1), be1);
        float o10 = __fadd_rn(__fmul_rn(__fmul_rn(g0, __fsub_rn(h10, mm0)), r0), be0);
        float o11 = __fadd_rn(__fmul_rn(__fmul_rn(g1, __fsub_rn(h11, mm1)), r1), be1);
        out[(size_t)(m0  )*H + n  ] = fmaxf(o00, 0.f);
        out[(size_t)(m0  )*H + n+1] = fmaxf(o01, 0.f);
        out[(size_t)(m0+1)*H + n  ] = fmaxf(o10, 0.f);
        out[(size_t)(m0+1)*H + n+1] = fmaxf(o11, 0.f);
    }
}

// ---------------- heads: x2, softmax, weighted sums, kinematics -------------
__global__ void heads_kernel(const float* __restrict__ xx,
                             const float* __restrict__ W2,
                             const float* __restrict__ b2,
                             const float* __restrict__ W100,
                             const float* __restrict__ b100,
                             float* __restrict__ out) {
    int b = blockIdx.x, tid = threadIdx.x;   // 256 threads
    __shared__ float sh[H];
    __shared__ float s_logit[NP];
    __shared__ float s_x2[2];
    for (int nn = tid; nn < H; nn += 256) sh[nn] = d_hA[(size_t)b*H + nn];
    __syncthreads();
    if (tid < NP) {
        float acc = 0.f;
        for (int nn = 0; nn < H; nn++)
            acc = __fmaf_rn(sh[nn], W100[(size_t)nn*NP + tid], acc);
        s_logit[tid] = __fadd_rn(acc, b100[tid]);
    } else if (tid < NP + 2) {
        int j = tid - NP;
        float acc = 0.f;
        for (int nn = 0; nn < H; nn++)
            acc = __fmaf_rn(sh[nn], W2[nn*2 + j], acc);
        s_x2[j] = __fadd_rn(acc, b2[j]);
    }
    __syncthreads();
    if (tid == 0) {
        float mx = s_logit[0];
        for (int i = 1; i < NP; i++) mx = fmaxf(mx, s_logit[i]);
        float sum = 0.f;
        for (int i = 0; i < NP; i++) { float ev = expf(__fsub_rn(s_logit[i], mx)); s_logit[i] = ev; sum += ev; }
        const float* xb = xx + (size_t)b*NP*F_IN;
        float px = 0.f, py = 0.f, pz = 0.f, E = 0.f;
        for (int i = 0; i < NP; i++) {
            float w = __fmul_rn(__fdiv_rn(s_logit[i], sum), xb[i*F_IN + 7]);   // * VALID
            px = __fmaf_rn(xb[i*F_IN + 3], w, px);
            py = __fmaf_rn(xb[i*F_IN + 4], w, py);
            pz = __fmaf_rn(xb[i*F_IN + 5], w, pz);
            E  = __fmaf_rn(xb[i*F_IN + 6], w, E);
        }
        float px2 = __fmul_rn(px,px), py2 = __fmul_rn(py,py), pz2 = __fmul_rn(pz,pz);
        float pt = __fsqrt_rn(__fadd_rn(px2, py2));
        float mass2 = __fsub_rn(__fsub_rn(__fsub_rn(__fmul_rn(E,E), px2), py2), pz2);
        float absp = __fsqrt_rn(__fadd_rn(__fadd_rn(px2, py2), pz2));
        float denom = (absp == 0.f) ? 1.f : absp;
        float cosT  = (absp == 0.f) ? 1.f : __fdiv_rn(pz, denom);
        bool ok = (__fmul_rn(cosT,cosT) < 1.f);
        float ratio = ok ? __fdiv_rn(__fsub_rn(1.f, cosT), __fadd_rn(1.f, cosT)) : 1.f;
        float eta = ok ? __fmul_rn(-0.5f, logf(ratio)) : 0.f;
        float phi = (px == 0.f && py == 0.f) ? 0.f : atan2f(py, px);
        out[b*6+0] = s_x2[0];
        out[b*6+1] = s_x2[1];
        out[b*6+2] = pt;
        out[b*6+3] = eta;
        out[b*6+4] = phi;
        out[b*6+5] = mass2;
    }
}

// ---------------- launch ----------------
extern "C" void kernel_launch(void* const* d_in, const int* in_sizes, int n_in,
                              void* d_out, int out_size) {
    const float* xx    = (const float*)d_in[0];
    const float* emb1  = (const float*)d_in[1];
    const float* emb2  = (const float*)d_in[2];
    const float* emb3  = (const float*)d_in[3];
    const float* mean  = (const float*)d_in[4];
    const float* stdv  = (const float*)d_in[5];
    const float* vmin  = (const float*)d_in[6];
    const float* vmax  = (const float*)d_in[7];
    const float* W0    = (const float*)d_in[8];
    const float* b0    = (const float*)d_in[9];
    const float* Wh    = (const float*)d_in[10];
    const float* bh    = (const float*)d_in[11];
    const float* gamma = (const float*)d_in[12];
    const float* beta  = (const float*)d_in[13];
    const float* mmean = (const float*)d_in[14];
    const float* mvar  = (const float*)d_in[15];
    const float* Wc    = (const float*)d_in[16];
    const float* bc    = (const float*)d_in[17];
    const float* W2    = (const float*)d_in[18];
    const float* b2    = (const float*)d_in[19];
    const float* W100  = (const float*)d_in[20];
    const float* b100  = (const float*)d_in[21];

    float *pG, *pA, *pB;
    cudaGetSymbolAddress((void**)&pG, d_g);
    cudaGetSymbolAddress((void**)&pA, d_hA);
    cudaGetSymbolAddress((void**)&pB, d_hB);

    prep_kernel<<<(B*NP + 255)/256, 256>>>(xx, emb1, emb2, emb3, mean, stdv, vmin, vmax);

    const int GRID_L = (H + 31) / 32;   // 113
    for (int it = 0; it < NP; it++) {
        knn_kernel<<<B, 128>>>(Wc, bc, it > 0 ? 1 : 0);
        layer_kernel<<<GRID_L, 256>>>(pG, GDIM, W0, b0,
                                      gamma, beta, mmean, mvar, pA);
        layer_kernel<<<GRID_L, 256>>>(pA, H, Wh + 0*(size_t)H*H, bh + 0*H,
                                      gamma + 1*H, beta + 1*H, mmean + 1*H, mvar + 1*H, pB);
        layer_kernel<<<GRID_L, 256>>>(pB, H, Wh + 1*(size_t)H*H, bh + 1*H,
                                      gamma + 2*H, beta + 2*H, mmean + 2*H, mvar + 2*H, pA);
        layer_kernel<<<GRID_L, 256>>>(pA, H, Wh + 2*(size_t)H*H, bh + 2*H,
                                      gamma + 3*H, beta + 3*H, mmean + 3*H, mvar + 3*H, pB);
        layer_kernel<<<GRID_L, 256>>>(pB, H, Wh + 3*(size_t)H*H, bh + 3*H,
                                      gamma + 4*H, beta + 4*H, mmean + 4*H, mvar + 4*H, pA);
    }

    heads_kernel<<<B, 256>>>(xx, W2, b2, W100, b100, (float*)d_out);
}

// round 7
// speedup vs baseline: 4.6464x; 4.6464x over previous
#include <cuda_runtime.h>
#include <math.h>

#define B    32
#define NP   100
#define F_IN 36
#define FC   40
#define KNN  11
#define GDIM 440
#define H    3600
#define NLAY 5
#define EPSB 0.001f
#define SPLITK 4
#define TILEK  32

typedef unsigned long long u64;

// ---------------- device scratch ----------------
__device__ float d_xfeat[B*NP*FC];
__device__ float d_g[B*GDIM];
__device__ float d_hA[B*H];
__device__ float d_hB[B*H];
__device__ float d_c2[B*2];
__device__ float d_partS[SPLITK*B*H];
__device__ float d_partC[SPLITK*B*H];
__device__ volatile unsigned g_gen;
__device__ unsigned g_cnt;

// ---------------- packed f32x2 helpers ----------------
__device__ __forceinline__ u64 mul2(u64 a, u64 b) {
    u64 d; asm("mul.rn.f32x2 %0,%1,%2;" : "=l"(d) : "l"(a), "l"(b)); return d;
}
__device__ __forceinline__ u64 add2(u64 a, u64 b) {
    u64 d; asm("add.rn.f32x2 %0,%1,%2;" : "=l"(d) : "l"(a), "l"(b)); return d;
}
__device__ __forceinline__ u64 fma2v(u64 a, u64 b, u64 c) {
    u64 d; asm("fma.rn.f32x2 %0,%1,%2,%3;" : "=l"(d) : "l"(a), "l"(b), "l"(c)); return d;
}
__device__ __forceinline__ u64 dup2(float a) {
    u64 d; asm("mov.b64 %0,{%1,%1};" : "=l"(d) : "f"(a)); return d;
}
__device__ __forceinline__ void unpack2(u64 v, float &lo, float &hi) {
    asm("mov.b64 {%0,%1}, %2;" : "=f"(lo), "=f"(hi) : "l"(v));
}
#define SGN2 0x8000000080000000ull
#define KM1  0xBF800000BF800000ull   /* packed (-1.0f, -1.0f) */

// EXACT compensated accumulate (TwoProd + Kahan), packed lanes — r4-proven.
__device__ __forceinline__ void kdot2(u64 &s, u64 &c, u64 a, u64 w) {
    u64 p  = mul2(a, w);
    u64 ep = fma2v(a, w, p ^ SGN2);   // exact product low part
    u64 y  = fma2v(c, KM1, p);        // p - c
    u64 t  = add2(s, y);
    u64 z  = fma2v(s, KM1, t);        // t - s
    c = fma2v(y, KM1, z);             // (t-s) - y
    c = fma2v(ep, KM1, c);            // fold product error
    s = t;
}

// ---------------- grid barrier (graph-replay safe: monotonic gen) -----------
__device__ __forceinline__ void grid_sync(unsigned nblocks) {
    __syncthreads();
    if (threadIdx.x == 0) {
        unsigned g = g_gen;
        __threadfence();
        if (atomicAdd(&g_cnt, 1u) == nblocks - 1u) {
            g_cnt = 0;
            __threadfence();
            g_gen = g + 1u;
        } else {
            while (g_gen == g) { }
        }
        __threadfence();
    }
    __syncthreads();
}

// ---------------- prep: features + init c2 (bit-exact elementwise) ----------
__global__ void prep_kernel(const float* __restrict__ xx,
                            const float* __restrict__ emb1,
                            const float* __restrict__ emb2,
                            const float* __restrict__ emb3,
                            const float* __restrict__ mean,
                            const float* __restrict__ stdv,
                            const float* __restrict__ vmin,
                            const float* __restrict__ vmax) {
    int idx = blockIdx.x*blockDim.x + threadIdx.x;
    if (idx >= B*NP) return;
    int b = idx / NP, p = idx % NP;
    const float* row = xx + (size_t)(b*NP + p)*F_IN;
    float* orow = d_xfeat + (size_t)(b*NP + p)*FC;
    int i1 = (int)fabsf(row[0]);
    int i2 = (int)fabsf(row[1]);
    int i3 = (int)fabsf(row[2]);
    orow[0] = emb1[i1*2+0]; orow[1] = emb1[i1*2+1];
    orow[2] = emb2[i2*2+0]; orow[3] = emb2[i2*2+1];
    orow[4] = emb3[i3*2+0]; orow[5] = emb3[i3*2+1];
    for (int f = 2; f < F_IN; f++) {
        float v = row[f];
        if (f >= 3) {
            float y = __fdiv_rn(__fsub_rn(v, mean[f]), stdv[f]);
            y = fminf(fmaxf(y, -5.0f), 5.0f);
            float sc = __fdiv_rn(2.0f, __fsub_rn(vmax[f], vmin[f]));
            float y2 = __fsub_rn(__fmul_rn(sc, __fsub_rn(y, vmin[f])), 1.0f);
            y2 = fminf(fmaxf(y2, -1.0f), 1.0f);
            v = y2;
        }
        orow[6 + (f - 2)] = v;
    }
    if (p == 0) {
        d_c2[b*2+0] = orow[12];   // ETA_C
        d_c2[b*2+1] = orow[13];   // PHI_C
    }
}

// ---------------- knn: c2 exact (lane TwoProd+Kahan, double merge) ----------
__global__ void knn_kernel(const float* __restrict__ Wc,
                           const float* __restrict__ bc,
                           int compute_c2) {
    int b = blockIdx.x;
    int tid = threadIdx.x;   // 128 threads
    __shared__ float s_ref[2];
    __shared__ float s_d[NP];
    __shared__ int   s_idx[KNN];

    if (compute_c2) {
        int w = tid >> 5, lane = tid & 31;
        if (w < 2) {
            const float* hrow = d_hA + (size_t)b*H;
            int st = lane * 113;
            int en = st + 113; if (en > H) en = H;
            // exact compensated lane partial
            float s = 0.f, c = 0.f;
            for (int k = st; k < en; k++) {
                float a = hrow[k], ww = Wc[k*2+w];
                float p  = __fmul_rn(a, ww);
                float ep = __fmaf_rn(a, ww, -p);
                float y  = __fsub_rn(p, c);
                float t  = __fadd_rn(s, y);
                c = __fsub_rn(__fsub_rn(t, s), y);
                c = __fsub_rn(c, ep);
                s = t;
            }
            // double-precision merge of 32 (s, c) pairs (exact)
            double acc = 0.0;
            #pragma unroll
            for (int src = 0; src < 32; src++) {
                float si = __shfl_sync(0xffffffffu, s, src);
                float ci = __shfl_sync(0xffffffffu, c, src);
                acc += (double)si - (double)ci;
            }
            if (lane == 0)
                s_ref[w] = __fadd_rn((float)acc, bc[w]);
        }
    } else {
        if (tid < 2) s_ref[tid] = d_c2[b*2+tid];
    }
    __syncthreads();

    if (tid < NP) {
        float dx = __fsub_rn(d_xfeat[(size_t)(b*NP + tid)*FC + 12], s_ref[0]);
        float dy = __fsub_rn(d_xfeat[(size_t)(b*NP + tid)*FC + 13], s_ref[1]);
        s_d[tid] = __fsqrt_rn(__fadd_rn(__fmul_rn(dx,dx), __fmul_rn(dy,dy)));
    }
    __syncthreads();
    if (tid < NP) {
        float mine = s_d[tid];
        int rank = 0;
        #pragma unroll 4
        for (int j = 0; j < NP; j++) {
            float dj = s_d[j];
            rank += (dj < mine) || (dj == mine && j < tid);  // stable tie-break
        }
        if (rank < KNN) s_idx[rank] = tid;
    }
    __syncthreads();
    for (int i = tid; i < GDIM; i += 128) {
        int k = i / FC, f = i - k*FC;
        d_g[(size_t)b*GDIM + i] = d_xfeat[(size_t)(b*NP + s_idx[k])*FC + f];
    }
}

// ---------------- fused layer: exact split-K GEMM + barrier + combine -------
// grid (113, SPLITK), 256 thr. Warp: lane = M-row, warp covers 4 cols.
// Phase 1: EXACT (TwoProd+Kahan) partials -> d_partS/C.
// Phase 2 (after grid barrier): double-precision combine + bias + BN + ReLU.
__global__ void __launch_bounds__(256, 4)
layer_kernel(const float* __restrict__ A, int Kd,
             const float* __restrict__ W,
             const float* __restrict__ bias,
             const float* __restrict__ gamma,
             const float* __restrict__ beta,
             const float* __restrict__ mmean,
             const float* __restrict__ mvar,
             float* __restrict__ out) {
    __shared__ float sAT[TILEK*33];                 // [k][m], pad 33
    __shared__ __align__(16) float sW[TILEK][32];   // [k][col]
    int tid  = threadIdx.x;
    int lane = tid & 31;          // M row
    int wrp  = tid >> 5;          // 0..7 -> 4 cols each
    int n0   = blockIdx.x * 32;
    int kb   = blockIdx.y;
    int cloc = wrp * 4;           // local col
    int c0   = n0 + cloc;         // global col

    int Kc = ((Kd + SPLITK - 1)/SPLITK + 7) & ~7;
    int kstart = kb * Kc;
    int kend   = kstart + Kc; if (kend > Kd) kend = Kd;

    u64 S0 = 0, C0 = 0, S1 = 0, C1 = 0;

    int am = tid >> 3;            // A row for staging
    int aq = (tid & 7) << 2;      // A k-offset (float4)
    int wk = tid >> 3;            // W k-row for staging
    int wq = (tid & 7) << 2;      // W col offset (float4)

    for (int k0 = kstart; k0 < kend; k0 += TILEK) {
        int klen = kend - k0; if (klen > TILEK) klen = TILEK;  // mult of 8
        if (aq < klen) {
            float4 v = *reinterpret_cast<const float4*>(A + (size_t)am*Kd + k0 + aq);
            sAT[(aq+0)*33 + am] = v.x;
            sAT[(aq+1)*33 + am] = v.y;
            sAT[(aq+2)*33 + am] = v.z;
            sAT[(aq+3)*33 + am] = v.w;
        }
        if (wk < klen) {
            int nn = n0 + wq;
            float4 w = make_float4(0.f,0.f,0.f,0.f);
            if (nn < H)
                w = *reinterpret_cast<const float4*>(W + (size_t)(k0+wk)*H + nn);
            *reinterpret_cast<float4*>(&sW[wk][wq]) = w;
        }
        __syncthreads();
        #pragma unroll 4
        for (int kk = 0; kk < klen; kk++) {
            float a = sAT[kk*33 + lane];
            u64 a2 = dup2(a);
            ulonglong2 w = *reinterpret_cast<const ulonglong2*>(&sW[kk][cloc]);
            kdot2(S0, C0, a2, w.x);
            kdot2(S1, C1, a2, w.y);
        }
        __syncthreads();
    }

    if (c0 < H) {
        size_t i0 = ((size_t)kb*B + lane)*H + c0;
        *reinterpret_cast<u64*>(&d_partS[i0])   = S0;
        *reinterpret_cast<u64*>(&d_partC[i0])   = C0;
        *reinterpret_cast<u64*>(&d_partS[i0+2]) = S1;
        *reinterpret_cast<u64*>(&d_partC[i0+2]) = C1;
    }

    grid_sync(gridDim.x * gridDim.y);

    // phase 2: double-precision combine (exact) + bias + BN + ReLU
    int bid = blockIdx.y * gridDim.x + blockIdx.x;
    int gi  = bid * 256 + tid;
    if (gi < B*H) {
        int n = gi % H;
        double acc = 0.0;
        #pragma unroll
        for (int k = 0; k < SPLITK; k++) {
            acc += (double)d_partS[k*(B*H) + gi];
            acc -= (double)d_partC[k*(B*H) + gi];
        }
        float h = __fadd_rn((float)acc, bias[n]);
        float r = __fdiv_rn(1.0f, __fsqrt_rn(__fadd_rn(mvar[n], EPSB)));
        float o = __fadd_rn(__fmul_rn(__fmul_rn(gamma[n], __fsub_rn(h, mmean[n])), r), beta[n]);
        out[gi] = fmaxf(o, 0.f);
    }
}

// ---------------- heads ------------------------------------------------------
__global__ void heads_kernel(const float* __restrict__ xx,
                             const float* __restrict__ W2,
                             const float* __restrict__ b2,
                             const float* __restrict__ W100,
                             const float* __restrict__ b100,
                             float* __restrict__ out) {
    int b = blockIdx.x, tid = threadIdx.x;   // 256 threads
    __shared__ float sh[H];
    __shared__ float s_logit[NP];
    __shared__ float s_x2[2];
    for (int nn = tid; nn < H; nn += 256) sh[nn] = d_hA[(size_t)b*H + nn];
    __syncthreads();
    if (tid < NP) {
        float acc = 0.f;
        for (int nn = 0; nn < H; nn++)
            acc = __fmaf_rn(sh[nn], W100[(size_t)nn*NP + tid], acc);
        s_logit[tid] = __fadd_rn(acc, b100[tid]);
    } else if (tid < NP + 2) {
        int j = tid - NP;
        float acc = 0.f;
        for (int nn = 0; nn < H; nn++)
            acc = __fmaf_rn(sh[nn], W2[nn*2 + j], acc);
        s_x2[j] = __fadd_rn(acc, b2[j]);
    }
    __syncthreads();
    if (tid == 0) {
        float mx = s_logit[0];
        for (int i = 1; i < NP; i++) mx = fmaxf(mx, s_logit[i]);
        float sum = 0.f;
        for (int i = 0; i < NP; i++) { float ev = expf(__fsub_rn(s_logit[i], mx)); s_logit[i] = ev; sum += ev; }
        const float* xb = xx + (size_t)b*NP*F_IN;
        float px = 0.f, py = 0.f, pz = 0.f, E = 0.f;
        for (int i = 0; i < NP; i++) {
            float w = __fmul_rn(__fdiv_rn(s_logit[i], sum), xb[i*F_IN + 7]);
            px = __fmaf_rn(xb[i*F_IN + 3], w, px);
            py = __fmaf_rn(xb[i*F_IN + 4], w, py);
            pz = __fmaf_rn(xb[i*F_IN + 5], w, pz);
            E  = __fmaf_rn(xb[i*F_IN + 6], w, E);
        }
        float px2 = __fmul_rn(px,px), py2 = __fmul_rn(py,py), pz2 = __fmul_rn(pz,pz);
        float pt = __fsqrt_rn(__fadd_rn(px2, py2));
        float mass2 = __fsub_rn(__fsub_rn(__fsub_rn(__fmul_rn(E,E), px2), py2), pz2);
        float absp = __fsqrt_rn(__fadd_rn(__fadd_rn(px2, py2), pz2));
        float denom = (absp == 0.f) ? 1.f : absp;
        float cosT  = (absp == 0.f) ? 1.f : __fdiv_rn(pz, denom);
        bool ok = (__fmul_rn(cosT,cosT) < 1.f);
        float ratio = ok ? __fdiv_rn(__fsub_rn(1.f, cosT), __fadd_rn(1.f, cosT)) : 1.f;
        float eta = ok ? __fmul_rn(-0.5f, logf(ratio)) : 0.f;
        float phi = (px == 0.f && py == 0.f) ? 0.f : atan2f(py, px);
        out[b*6+0] = s_x2[0];
        out[b*6+1] = s_x2[1];
        out[b*6+2] = pt;
        out[b*6+3] = eta;
        out[b*6+4] = phi;
        out[b*6+5] = mass2;
    }
}

// ---------------- launch ----------------
extern "C" void kernel_launch(void* const* d_in, const int* in_sizes, int n_in,
                              void* d_out, int out_size) {
    const float* xx    = (const float*)d_in[0];
    const float* emb1  = (const float*)d_in[1];
    const float* emb2  = (const float*)d_in[2];
    const float* emb3  = (const float*)d_in[3];
    const float* mean  = (const float*)d_in[4];
    const float* stdv  = (const float*)d_in[5];
    const float* vmin  = (const float*)d_in[6];
    const float* vmax  = (const float*)d_in[7];
    const float* W0    = (const float*)d_in[8];
    const float* b0    = (const float*)d_in[9];
    const float* Wh    = (const float*)d_in[10];
    const float* bh    = (const float*)d_in[11];
    const float* gamma = (const float*)d_in[12];
    const float* beta  = (const float*)d_in[13];
    const float* mmean = (const float*)d_in[14];
    const float* mvar  = (const float*)d_in[15];
    const float* Wc    = (const float*)d_in[16];
    const float* bc    = (const float*)d_in[17];
    const float* W2    = (const float*)d_in[18];
    const float* b2    = (const float*)d_in[19];
    const float* W100  = (const float*)d_in[20];
    const float* b100  = (const float*)d_in[21];

    float *pG, *pA, *pB;
    cudaGetSymbolAddress((void**)&pG, d_g);
    cudaGetSymbolAddress((void**)&pA, d_hA);
    cudaGetSymbolAddress((void**)&pB, d_hB);

    prep_kernel<<<(B*NP + 255)/256, 256>>>(xx, emb1, emb2, emb3, mean, stdv, vmin, vmax);

    const dim3 GL((H + 31)/32, SPLITK);     // (113, 4) -> 452 blocks (co-resident)

    for (int it = 0; it < NP; it++) {
        knn_kernel<<<B, 128>>>(Wc, bc, it > 0 ? 1 : 0);

        layer_kernel<<<GL, 256>>>(pG, GDIM, W0, b0,
                                  gamma, beta, mmean, mvar, pA);
        layer_kernel<<<GL, 256>>>(pA, H, Wh + 0*(size_t)H*H, bh + 0*H,
                                  gamma + 1*H, beta + 1*H, mmean + 1*H, mvar + 1*H, pB);
        layer_kernel<<<GL, 256>>>(pB, H, Wh + 1*(size_t)H*H, bh + 1*H,
                                  gamma + 2*H, beta + 2*H, mmean + 2*H, mvar + 2*H, pA);
        layer_kernel<<<GL, 256>>>(pA, H, Wh + 2*(size_t)H*H, bh + 2*H,
                                  gamma + 3*H, beta + 3*H, mmean + 3*H, mvar + 3*H, pB);
        layer_kernel<<<GL, 256>>>(pB, H, Wh + 3*(size_t)H*H, bh + 3*H,
                                  gamma + 4*H, beta + 4*H, mmean + 4*H, mvar + 4*H, pA);
    }

    heads_kernel<<<B, 256>>>(xx, W2, b2, W100, b100, (float*)d_out);
}

// round 8
// speedup vs baseline: 7.0828x; 1.5244x over previous
#include <cuda_runtime.h>
#include <math.h>

#define B    32
#define NP   100
#define F_IN 36
#define FC   40
#define KNN  11
#define GDIM 440
#define H    3600
#define NLAY 5
#define EPSB 0.001f
#define SPLITK 4
#define TILEK  32

typedef unsigned long long u64;

// ---------------- device scratch ----------------
__device__ float d_xfeat[B*NP*FC];
__device__ float d_g[B*GDIM];
__device__ float d_hA[B*H];
__device__ float d_hB[B*H];
__device__ float d_c2[B*2];
__device__ float d_partS[SPLITK*B*H];
__device__ float d_partC[SPLITK*B*H];   // holds NC (negated compensation)
__device__ volatile unsigned g_gen;
__device__ unsigned g_cnt;

// ---------------- packed f32x2 helpers ----------------
__device__ __forceinline__ u64 add2(u64 a, u64 b) {
    u64 d; asm("add.rn.f32x2 %0,%1,%2;" : "=l"(d) : "l"(a), "l"(b)); return d;
}
__device__ __forceinline__ u64 fma2v(u64 a, u64 b, u64 c) {
    u64 d; asm("fma.rn.f32x2 %0,%1,%2,%3;" : "=l"(d) : "l"(a), "l"(b), "l"(c)); return d;
}
__device__ __forceinline__ u64 dup2(float a) {
    u64 d; asm("mov.b64 %0,{%1,%1};" : "=l"(d) : "f"(a)); return d;
}
#define KM1 0xBF800000BF800000ull   /* packed (-1.0f, -1.0f) */

// Kahan-FMA accumulate (Scheme X): product fused into Kahan y-term.
// State: S (sum), NC (negated compensation). True value ~= S + NC.
// 4 FMA-pipe ops per call; noise ~1 ulp of final sum over K=3600.
__device__ __forceinline__ void kfma2(u64 &S, u64 &NC, u64 a, u64 w) {
    u64 y = fma2v(a, w, NC);     // a*w - c
    u64 t = add2(S, y);
    u64 z = fma2v(S, KM1, t);    // t - S
    NC = fma2v(z, KM1, y);       // y - z  (= -c_new)
    S = t;
}

// ---------------- grid barrier (graph-replay safe: monotonic gen) -----------
__device__ __forceinline__ void grid_sync(unsigned nblocks) {
    __syncthreads();
    if (threadIdx.x == 0) {
        unsigned g = g_gen;
        __threadfence();
        if (atomicAdd(&g_cnt, 1u) == nblocks - 1u) {
            g_cnt = 0;
            __threadfence();
            g_gen = g + 1u;
        } else {
            while (g_gen == g) { }
        }
        __threadfence();
    }
    __syncthreads();
}

// ---------------- prep: features + init c2 (bit-exact elementwise) ----------
__global__ void prep_kernel(const float* __restrict__ xx,
                            const float* __restrict__ emb1,
                            const float* __restrict__ emb2,
                            const float* __restrict__ emb3,
                            const float* __restrict__ mean,
                            const float* __restrict__ stdv,
                            const float* __restrict__ vmin,
                            const float* __restrict__ vmax) {
    int idx = blockIdx.x*blockDim.x + threadIdx.x;
    if (idx >= B*NP) return;
    int b = idx / NP, p = idx % NP;
    const float* row = xx + (size_t)(b*NP + p)*F_IN;
    float* orow = d_xfeat + (size_t)(b*NP + p)*FC;
    int i1 = (int)fabsf(row[0]);
    int i2 = (int)fabsf(row[1]);
    int i3 = (int)fabsf(row[2]);
    orow[0] = emb1[i1*2+0]; orow[1] = emb1[i1*2+1];
    orow[2] = emb2[i2*2+0]; orow[3] = emb2[i2*2+1];
    orow[4] = emb3[i3*2+0]; orow[5] = emb3[i3*2+1];
    for (int f = 2; f < F_IN; f++) {
        float v = row[f];
        if (f >= 3) {
            float y = __fdiv_rn(__fsub_rn(v, mean[f]), stdv[f]);
            y = fminf(fmaxf(y, -5.0f), 5.0f);
            float sc = __fdiv_rn(2.0f, __fsub_rn(vmax[f], vmin[f]));
            float y2 = __fsub_rn(__fmul_rn(sc, __fsub_rn(y, vmin[f])), 1.0f);
            y2 = fminf(fmaxf(y2, -1.0f), 1.0f);
            v = y2;
        }
        orow[6 + (f - 2)] = v;
    }
    if (p == 0) {
        d_c2[b*2+0] = orow[12];   // ETA_C
        d_c2[b*2+1] = orow[13];   // PHI_C
    }
}

// ---------------- knn: c2 exact (lane TwoProd+Kahan, double merge) ----------
__global__ void knn_kernel(const float* __restrict__ Wc,
                           const float* __restrict__ bc,
                           int compute_c2) {
    int b = blockIdx.x;
    int tid = threadIdx.x;   // 128 threads
    __shared__ float s_ref[2];
    __shared__ float s_d[NP];
    __shared__ int   s_idx[KNN];

    if (compute_c2) {
        int w = tid >> 5, lane = tid & 31;
        if (w < 2) {
            const float* hrow = d_hA + (size_t)b*H;
            int st = lane * 113;
            int en = st + 113; if (en > H) en = H;
            float s = 0.f, c = 0.f;
            for (int k = st; k < en; k++) {
                float a = hrow[k], ww = Wc[k*2+w];
                float p  = __fmul_rn(a, ww);
                float ep = __fmaf_rn(a, ww, -p);
                float y  = __fsub_rn(p, c);
                float t  = __fadd_rn(s, y);
                c = __fsub_rn(__fsub_rn(t, s), y);
                c = __fsub_rn(c, ep);
                s = t;
            }
            double acc = 0.0;
            #pragma unroll
            for (int src = 0; src < 32; src++) {
                float si = __shfl_sync(0xffffffffu, s, src);
                float ci = __shfl_sync(0xffffffffu, c, src);
                acc += (double)si - (double)ci;
            }
            if (lane == 0)
                s_ref[w] = __fadd_rn((float)acc, bc[w]);
        }
    } else {
        if (tid < 2) s_ref[tid] = d_c2[b*2+tid];
    }
    __syncthreads();

    if (tid < NP) {
        float dx = __fsub_rn(d_xfeat[(size_t)(b*NP + tid)*FC + 12], s_ref[0]);
        float dy = __fsub_rn(d_xfeat[(size_t)(b*NP + tid)*FC + 13], s_ref[1]);
        s_d[tid] = __fsqrt_rn(__fadd_rn(__fmul_rn(dx,dx), __fmul_rn(dy,dy)));
    }
    __syncthreads();
    if (tid < NP) {
        float mine = s_d[tid];
        int rank = 0;
        #pragma unroll 4
        for (int j = 0; j < NP; j++) {
            float dj = s_d[j];
            rank += (dj < mine) || (dj == mine && j < tid);  // stable tie-break
        }
        if (rank < KNN) s_idx[rank] = tid;
    }
    __syncthreads();
    for (int i = tid; i < GDIM; i += 128) {
        int k = i / FC, f = i - k*FC;
        d_g[(size_t)b*GDIM + i] = d_xfeat[(size_t)(b*NP + s_idx[k])*FC + f];
    }
}

// ---------------- fused layer: split-K Kahan-FMA GEMM + barrier + combine ---
__global__ void __launch_bounds__(256, 4)
layer_kernel(const float* __restrict__ A, int Kd,
             const float* __restrict__ W,
             const float* __restrict__ bias,
             const float* __restrict__ gamma,
             const float* __restrict__ beta,
             const float* __restrict__ mmean,
             const float* __restrict__ mvar,
             float* __restrict__ out) {
    __shared__ float sAT[TILEK*33];                 // [k][m], pad 33
    __shared__ __align__(16) float sW[TILEK][32];   // [k][col]
    int tid  = threadIdx.x;
    int lane = tid & 31;          // M row
    int wrp  = tid >> 5;          // 0..7 -> 4 cols each
    int n0   = blockIdx.x * 32;
    int kb   = blockIdx.y;
    int cloc = wrp * 4;           // local col
    int c0   = n0 + cloc;         // global col

    int Kc = ((Kd + SPLITK - 1)/SPLITK + 7) & ~7;
    int kstart = kb * Kc;
    int kend   = kstart + Kc; if (kend > Kd) kend = Kd;

    u64 S0 = 0, N0 = 0, S1 = 0, N1 = 0;

    int am = tid >> 3;            // A row for staging
    int aq = (tid & 7) << 2;      // A k-offset (float4)
    int wk = tid >> 3;            // W k-row for staging
    int wq = (tid & 7) << 2;      // W col offset (float4)

    const float* sWc = &sW[0][cloc];

    for (int k0 = kstart; k0 < kend; k0 += TILEK) {
        int klen = kend - k0; if (klen > TILEK) klen = TILEK;  // mult of 8
        if (aq < klen) {
            float4 v = *reinterpret_cast<const float4*>(A + (size_t)am*Kd + k0 + aq);
            sAT[(aq+0)*33 + am] = v.x;
            sAT[(aq+1)*33 + am] = v.y;
            sAT[(aq+2)*33 + am] = v.z;
            sAT[(aq+3)*33 + am] = v.w;
        }
        if (wk < klen) {
            int nn = n0 + wq;
            float4 w = make_float4(0.f,0.f,0.f,0.f);
            if (nn < H)
                w = *reinterpret_cast<const float4*>(W + (size_t)(k0+wk)*H + nn);
            *reinterpret_cast<float4*>(&sW[wk][wq]) = w;
        }
        __syncthreads();
        if (klen == TILEK) {
            #pragma unroll
            for (int kk = 0; kk < TILEK; kk++) {
                u64 a2 = dup2(sAT[kk*33 + lane]);
                ulonglong2 w = *reinterpret_cast<const ulonglong2*>(sWc + kk*32);
                kfma2(S0, N0, a2, w.x);
                kfma2(S1, N1, a2, w.y);
            }
        } else {
            for (int kk = 0; kk < klen; kk++) {
                u64 a2 = dup2(sAT[kk*33 + lane]);
                ulonglong2 w = *reinterpret_cast<const ulonglong2*>(sWc + kk*32);
                kfma2(S0, N0, a2, w.x);
                kfma2(S1, N1, a2, w.y);
            }
        }
        __syncthreads();
    }

    if (c0 < H) {
        size_t i0 = ((size_t)kb*B + lane)*H + c0;
        *reinterpret_cast<u64*>(&d_partS[i0])   = S0;
        *reinterpret_cast<u64*>(&d_partC[i0])   = N0;
        *reinterpret_cast<u64*>(&d_partS[i0+2]) = S1;
        *reinterpret_cast<u64*>(&d_partC[i0+2]) = N1;
    }

    grid_sync(gridDim.x * gridDim.y);

    // phase 2: double-precision combine (exact) + bias + BN + ReLU
    int bid = blockIdx.y * gridDim.x + blockIdx.x;
    int gi  = bid * 256 + tid;
    if (gi < B*H) {
        int n = gi % H;
        double acc = 0.0;
        #pragma unroll
        for (int k = 0; k < SPLITK; k++) {
            acc += (double)d_partS[k*(B*H) + gi];
            acc += (double)d_partC[k*(B*H) + gi];   // NC already negated
        }
        float h = __fadd_rn((float)acc, bias[n]);
        float r = __fdiv_rn(1.0f, __fsqrt_rn(__fadd_rn(mvar[n], EPSB)));
        float o = __fadd_rn(__fmul_rn(__fmul_rn(gamma[n], __fsub_rn(h, mmean[n])), r), beta[n]);
        out[gi] = fmaxf(o, 0.f);
    }
}

// ---------------- heads ------------------------------------------------------
__global__ void heads_kernel(const float* __restrict__ xx,
                             const float* __restrict__ W2,
                             const float* __restrict__ b2,
                             const float* __restrict__ W100,
                             const float* __restrict__ b100,
                             float* __restrict__ out) {
    int b = blockIdx.x, tid = threadIdx.x;   // 256 threads
    __shared__ float sh[H];
    __shared__ float s_logit[NP];
    __shared__ float s_x2[2];
    for (int nn = tid; nn < H; nn += 256) sh[nn] = d_hA[(size_t)b*H + nn];
    __syncthreads();
    if (tid < NP) {
        float acc = 0.f;
        for (int nn = 0; nn < H; nn++)
            acc = __fmaf_rn(sh[nn], W100[(size_t)nn*NP + tid], acc);
        s_logit[tid] = __fadd_rn(acc, b100[tid]);
    } else if (tid < NP + 2) {
        int j = tid - NP;
        float acc = 0.f;
        for (int nn = 0; nn < H; nn++)
            acc = __fmaf_rn(sh[nn], W2[nn*2 + j], acc);
        s_x2[j] = __fadd_rn(acc, b2[j]);
    }
    __syncthreads();
    if (tid == 0) {
        float mx = s_logit[0];
        for (int i = 1; i < NP; i++) mx = fmaxf(mx, s_logit[i]);
        float sum = 0.f;
        for (int i = 0; i < NP; i++) { float ev = expf(__fsub_rn(s_logit[i], mx)); s_logit[i] = ev; sum += ev; }
        const float* xb = xx + (size_t)b*NP*F_IN;
        float px = 0.f, py = 0.f, pz = 0.f, E = 0.f;
        for (int i = 0; i < NP; i++) {
            float w = __fmul_rn(__fdiv_rn(s_logit[i], sum), xb[i*F_IN + 7]);
            px = __fmaf_rn(xb[i*F_IN + 3], w, px);
            py = __fmaf_rn(xb[i*F_IN + 4], w, py);
            pz = __fmaf_rn(xb[i*F_IN + 5], w, pz);
            E  = __fmaf_rn(xb[i*F_IN + 6], w, E);
        }
        float px2 = __fmul_rn(px,px), py2 = __fmul_rn(py,py), pz2 = __fmul_rn(pz,pz);
        float pt = __fsqrt_rn(__fadd_rn(px2, py2));
        float mass2 = __fsub_rn(__fsub_rn(__fsub_rn(__fmul_rn(E,E), px2), py2), pz2);
        float absp = __fsqrt_rn(__fadd_rn(__fadd_rn(px2, py2), pz2));
        float denom = (absp == 0.f) ? 1.f : absp;
        float cosT  = (absp == 0.f) ? 1.f : __fdiv_rn(pz, denom);
        bool ok = (__fmul_rn(cosT,cosT) < 1.f);
        float ratio = ok ? __fdiv_rn(__fsub_rn(1.f, cosT), __fadd_rn(1.f, cosT)) : 1.f;
        float eta = ok ? __fmul_rn(-0.5f, logf(ratio)) : 0.f;
        float phi = (px == 0.f && py == 0.f) ? 0.f : atan2f(py, px);
        out[b*6+0] = s_x2[0];
        out[b*6+1] = s_x2[1];
        out[b*6+2] = pt;
        out[b*6+3] = eta;
        out[b*6+4] = phi;
        out[b*6+5] = mass2;
    }
}

// ---------------- launch ----------------
extern "C" void kernel_launch(void* const* d_in, const int* in_sizes, int n_in,
                              void* d_out, int out_size) {
    const float* xx    = (const float*)d_in[0];
    const float* emb1  = (const float*)d_in[1];
    const float* emb2  = (const float*)d_in[2];
    const float* emb3  = (const float*)d_in[3];
    const float* mean  = (const float*)d_in[4];
    const float* stdv  = (const float*)d_in[5];
    const float* vmin  = (const float*)d_in[6];
    const float* vmax  = (const float*)d_in[7];
    const float* W0    = (const float*)d_in[8];
    const float* b0    = (const float*)d_in[9];
    const float* Wh    = (const float*)d_in[10];
    const float* bh    = (const float*)d_in[11];
    const float* gamma = (const float*)d_in[12];
    const float* beta  = (const float*)d_in[13];
    const float* mmean = (const float*)d_in[14];
    const float* mvar  = (const float*)d_in[15];
    const float* Wc    = (const float*)d_in[16];
    const float* bc    = (const float*)d_in[17];
    const float* W2    = (const float*)d_in[18];
    const float* b2    = (const float*)d_in[19];
    const float* W100  = (const float*)d_in[20];
    const float* b100  = (const float*)d_in[21];

    float *pG, *pA, *pB;
    cudaGetSymbolAddress((void**)&pG, d_g);
    cudaGetSymbolAddress((void**)&pA, d_hA);
    cudaGetSymbolAddress((void**)&pB, d_hB);

    prep_kernel<<<(B*NP + 255)/256, 256>>>(xx, emb1, emb2, emb3, mean, stdv, vmin, vmax);

    const dim3 GL((H + 31)/32, SPLITK);     // (113, 4) -> 452 blocks (co-resident)

    for (int it = 0; it < NP; it++) {
        knn_kernel<<<B, 128>>>(Wc, bc, it > 0 ? 1 : 0);

        layer_kernel<<<GL, 256>>>(pG, GDIM, W0, b0,
                                  gamma, beta, mmean, mvar, pA);
        layer_kernel<<<GL, 256>>>(pA, H, Wh + 0*(size_t)H*H, bh + 0*H,
                                  gamma + 1*H, beta + 1*H, mmean + 1*H, mvar + 1*H, pB);
        layer_kernel<<<GL, 256>>>(pB, H, Wh + 1*(size_t)H*H, bh + 1*H,
                                  gamma + 2*H, beta + 2*H, mmean + 2*H, mvar + 2*H, pA);
        layer_kernel<<<GL, 256>>>(pA, H, Wh + 2*(size_t)H*H, bh + 2*H,
                                  gamma + 3*H, beta + 3*H, mmean + 3*H, mvar + 3*H, pB);
        layer_kernel<<<GL, 256>>>(pB, H, Wh + 3*(size_t)H*H, bh + 3*H,
                                  gamma + 4*H, beta + 4*H, mmean + 4*H, mvar + 4*H, pA);
    }

    heads_kernel<<<B, 256>>>(xx, W2, b2, W100, b100, (float*)d_out);
}

// round 9
// speedup vs baseline: 8.4357x; 1.1910x over previous
#include <cuda_runtime.h>
#include <math.h>

#define B    32
#define NP   100
#define F_IN 36
#define FC   40
#define KNN  11
#define GDIM 440
#define H    3600
#define NLAY 5
#define EPSB 0.001f
#define SPLITK 4
#define TILEK  32

typedef unsigned long long u64;

// ---------------- device scratch ----------------
__device__ float d_xfeat[B*NP*FC];
__device__ float d_g[B*GDIM];
__device__ float d_hA[B*H];
__device__ float d_hB[B*H];
__device__ float d_c2[B*2];
__device__ float d_partS[SPLITK*B*H];
__device__ float d_partC[SPLITK*B*H];   // holds NC (negated compensation)
__device__ volatile unsigned g_gen;
__device__ unsigned g_cnt;

// ---------------- packed f32x2 helpers ----------------
__device__ __forceinline__ u64 add2(u64 a, u64 b) {
    u64 d; asm("add.rn.f32x2 %0,%1,%2;" : "=l"(d) : "l"(a), "l"(b)); return d;
}
__device__ __forceinline__ u64 fma2v(u64 a, u64 b, u64 c) {
    u64 d; asm("fma.rn.f32x2 %0,%1,%2,%3;" : "=l"(d) : "l"(a), "l"(b), "l"(c)); return d;
}
__device__ __forceinline__ u64 dup2(float a) {
    u64 d; asm("mov.b64 %0,{%1,%1};" : "=l"(d) : "f"(a)); return d;
}
#define KM1 0xBF800000BF800000ull   /* packed (-1.0f, -1.0f) */

// Chunk-2 Kahan-FMA: two products folded into the Kahan y-term.
// State: S (sum), NC (negated compensation). True value ~= S + NC.
// 5 FMA-pipe ops per 2 k-steps; noise ~1.6 ulp of final sum over K=3600.
__device__ __forceinline__ void kpair2(u64 &S, u64 &NC,
                                       u64 a0, u64 w0, u64 a1, u64 w1) {
    u64 p = fma2v(a0, w0, NC);   // a0*w0 - c
    u64 y = fma2v(a1, w1, p);    // + a1*w1
    u64 t = add2(S, y);
    u64 z = fma2v(S, KM1, t);    // t - S
    NC = fma2v(z, KM1, y);       // y - z  (= -c_new)
    S = t;
}

// ---------------- grid barrier (graph-replay safe: monotonic gen) -----------
__device__ __forceinline__ void grid_sync(unsigned nblocks) {
    __syncthreads();
    if (threadIdx.x == 0) {
        unsigned g = g_gen;
        __threadfence();
        if (atomicAdd(&g_cnt, 1u) == nblocks - 1u) {
            g_cnt = 0;
            __threadfence();
            g_gen = g + 1u;
        } else {
            while (g_gen == g) { }
        }
        __threadfence();
    }
    __syncthreads();
}

// ---------------- prep: features + init c2 (bit-exact elementwise) ----------
__global__ void prep_kernel(const float* __restrict__ xx,
                            const float* __restrict__ emb1,
                            const float* __restrict__ emb2,
                            const float* __restrict__ emb3,
                            const float* __restrict__ mean,
                            const float* __restrict__ stdv,
                            const float* __restrict__ vmin,
                            const float* __restrict__ vmax) {
    int idx = blockIdx.x*blockDim.x + threadIdx.x;
    if (idx >= B*NP) return;
    int b = idx / NP, p = idx % NP;
    const float* row = xx + (size_t)(b*NP + p)*F_IN;
    float* orow = d_xfeat + (size_t)(b*NP + p)*FC;
    int i1 = (int)fabsf(row[0]);
    int i2 = (int)fabsf(row[1]);
    int i3 = (int)fabsf(row[2]);
    orow[0] = emb1[i1*2+0]; orow[1] = emb1[i1*2+1];
    orow[2] = emb2[i2*2+0]; orow[3] = emb2[i2*2+1];
    orow[4] = emb3[i3*2+0]; orow[5] = emb3[i3*2+1];
    for (int f = 2; f < F_IN; f++) {
        float v = row[f];
        if (f >= 3) {
            float y = __fdiv_rn(__fsub_rn(v, mean[f]), stdv[f]);
            y = fminf(fmaxf(y, -5.0f), 5.0f);
            float sc = __fdiv_rn(2.0f, __fsub_rn(vmax[f], vmin[f]));
            float y2 = __fsub_rn(__fmul_rn(sc, __fsub_rn(y, vmin[f])), 1.0f);
            y2 = fminf(fmaxf(y2, -1.0f), 1.0f);
            v = y2;
        }
        orow[6 + (f - 2)] = v;
    }
    if (p == 0) {
        d_c2[b*2+0] = orow[12];   // ETA_C
        d_c2[b*2+1] = orow[13];   // PHI_C
    }
}

// ---------------- knn: c2 exact (lane TwoProd+Kahan, double merge) ----------
__global__ void knn_kernel(const float* __restrict__ Wc,
                           const float* __restrict__ bc,
                           int compute_c2) {
    int b = blockIdx.x;
    int tid = threadIdx.x;   // 128 threads
    __shared__ float s_ref[2];
    __shared__ float s_d[NP];
    __shared__ int   s_idx[KNN];

    if (compute_c2) {
        int w = tid >> 5, lane = tid & 31;
        if (w < 2) {
            const float* hrow = d_hA + (size_t)b*H;
            int st = lane * 113;
            int en = st + 113; if (en > H) en = H;
            float s = 0.f, c = 0.f;
            for (int k = st; k < en; k++) {
                float a = hrow[k], ww = Wc[k*2+w];
                float p  = __fmul_rn(a, ww);
                float ep = __fmaf_rn(a, ww, -p);
                float y  = __fsub_rn(p, c);
                float t  = __fadd_rn(s, y);
                c = __fsub_rn(__fsub_rn(t, s), y);
                c = __fsub_rn(c, ep);
                s = t;
            }
            double acc = 0.0;
            #pragma unroll
            for (int src = 0; src < 32; src++) {
                float si = __shfl_sync(0xffffffffu, s, src);
                float ci = __shfl_sync(0xffffffffu, c, src);
                acc += (double)si - (double)ci;
            }
            if (lane == 0)
                s_ref[w] = __fadd_rn((float)acc, bc[w]);
        }
    } else {
        if (tid < 2) s_ref[tid] = d_c2[b*2+tid];
    }
    __syncthreads();

    if (tid < NP) {
        float dx = __fsub_rn(d_xfeat[(size_t)(b*NP + tid)*FC + 12], s_ref[0]);
        float dy = __fsub_rn(d_xfeat[(size_t)(b*NP + tid)*FC + 13], s_ref[1]);
        s_d[tid] = __fsqrt_rn(__fadd_rn(__fmul_rn(dx,dx), __fmul_rn(dy,dy)));
    }
    __syncthreads();
    if (tid < NP) {
        float mine = s_d[tid];
        int rank = 0;
        #pragma unroll 4
        for (int j = 0; j < NP; j++) {
            float dj = s_d[j];
            rank += (dj < mine) || (dj == mine && j < tid);  // stable tie-break
        }
        if (rank < KNN) s_idx[rank] = tid;
    }
    __syncthreads();
    for (int i = tid; i < GDIM; i += 128) {
        int k = i / FC, f = i - k*FC;
        d_g[(size_t)b*GDIM + i] = d_xfeat[(size_t)(b*NP + s_idx[k])*FC + f];
    }
}

// ---------------- fused layer: split-K chunk-2 Kahan GEMM + combine ---------
__global__ void __launch_bounds__(256, 4)
layer_kernel(const float* __restrict__ A, int Kd,
             const float* __restrict__ W,
             const float* __restrict__ bias,
             const float* __restrict__ gamma,
             const float* __restrict__ beta,
             const float* __restrict__ mmean,
             const float* __restrict__ mvar,
             float* __restrict__ out) {
    __shared__ float sAT[TILEK*33];                 // [k][m], pad 33
    __shared__ __align__(16) float sW[TILEK][32];   // [k][col]
    int tid  = threadIdx.x;
    int lane = tid & 31;          // M row
    int wrp  = tid >> 5;          // 0..7 -> 4 cols each
    int n0   = blockIdx.x * 32;
    int kb   = blockIdx.y;
    int cloc = wrp * 4;           // local col
    int c0   = n0 + cloc;         // global col

    int Kc = ((Kd + SPLITK - 1)/SPLITK + 7) & ~7;
    int kstart = kb * Kc;
    int kend   = kstart + Kc; if (kend > Kd) kend = Kd;

    u64 S0 = 0, N0 = 0, S1 = 0, N1 = 0;

    int am = tid >> 3;            // A row for staging
    int aq = (tid & 7) << 2;      // A k-offset (float4)
    int wk = tid >> 3;            // W k-row for staging
    int wq = (tid & 7) << 2;      // W col offset (float4)

    const float* sWc = &sW[0][cloc];

    for (int k0 = kstart; k0 < kend; k0 += TILEK) {
        int klen = kend - k0; if (klen > TILEK) klen = TILEK;  // mult of 8
        if (aq < klen) {
            float4 v = *reinterpret_cast<const float4*>(A + (size_t)am*Kd + k0 + aq);
            sAT[(aq+0)*33 + am] = v.x;
            sAT[(aq+1)*33 + am] = v.y;
            sAT[(aq+2)*33 + am] = v.z;
            sAT[(aq+3)*33 + am] = v.w;
        }
        if (wk < klen) {
            int nn = n0 + wq;
            float4 w = make_float4(0.f,0.f,0.f,0.f);
            if (nn < H)
                w = *reinterpret_cast<const float4*>(W + (size_t)(k0+wk)*H + nn);
            *reinterpret_cast<float4*>(&sW[wk][wq]) = w;
        }
        __syncthreads();
        if (klen == TILEK) {
            #pragma unroll
            for (int kk = 0; kk < TILEK; kk += 2) {
                u64 a0 = dup2(sAT[(kk+0)*33 + lane]);
                u64 a1 = dup2(sAT[(kk+1)*33 + lane]);
                ulonglong2 wA = *reinterpret_cast<const ulonglong2*>(sWc + (kk+0)*32);
                ulonglong2 wB = *reinterpret_cast<const ulonglong2*>(sWc + (kk+1)*32);
                kpair2(S0, N0, a0, wA.x, a1, wB.x);
                kpair2(S1, N1, a0, wA.y, a1, wB.y);
            }
        } else {
            for (int kk = 0; kk < klen; kk += 2) {
                u64 a0 = dup2(sAT[(kk+0)*33 + lane]);
                u64 a1 = dup2(sAT[(kk+1)*33 + lane]);
                ulonglong2 wA = *reinterpret_cast<const ulonglong2*>(sWc + (kk+0)*32);
                ulonglong2 wB = *reinterpret_cast<const ulonglong2*>(sWc + (kk+1)*32);
                kpair2(S0, N0, a0, wA.x, a1, wB.x);
                kpair2(S1, N1, a0, wA.y, a1, wB.y);
            }
        }
        __syncthreads();
    }

    if (c0 < H) {
        size_t i0 = ((size_t)kb*B + lane)*H + c0;
        *reinterpret_cast<u64*>(&d_partS[i0])   = S0;
        *reinterpret_cast<u64*>(&d_partC[i0])   = N0;
        *reinterpret_cast<u64*>(&d_partS[i0+2]) = S1;
        *reinterpret_cast<u64*>(&d_partC[i0+2]) = N1;
    }

    grid_sync(gridDim.x * gridDim.y);

    // phase 2: double-precision combine (exact) + bias + BN + ReLU
    int bid = blockIdx.y * gridDim.x + blockIdx.x;
    int gi  = bid * 256 + tid;
    if (gi < B*H) {
        int n = gi % H;
        double acc = 0.0;
        #pragma unroll
        for (int k = 0; k < SPLITK; k++) {
            acc += (double)d_partS[k*(B*H) + gi];
            acc += (double)d_partC[k*(B*H) + gi];   // NC already negated
        }
        float h = __fadd_rn((float)acc, bias[n]);
        float r = __fdiv_rn(1.0f, __fsqrt_rn(__fadd_rn(mvar[n], EPSB)));
        float o = __fadd_rn(__fmul_rn(__fmul_rn(gamma[n], __fsub_rn(h, mmean[n])), r), beta[n]);
        out[gi] = fmaxf(o, 0.f);
    }
}

// ---------------- heads ------------------------------------------------------
__global__ void heads_kernel(const float* __restrict__ xx,
                             const float* __restrict__ W2,
                             const float* __restrict__ b2,
                             const float* __restrict__ W100,
                             const float* __restrict__ b100,
                             float* __restrict__ out) {
    int b = blockIdx.x, tid = threadIdx.x;   // 256 threads
    __shared__ float sh[H];
    __shared__ float s_logit[NP];
    __shared__ float s_x2[2];
    for (int nn = tid; nn < H; nn += 256) sh[nn] = d_hA[(size_t)b*H + nn];
    __syncthreads();
    if (tid < NP) {
        float acc = 0.f;
        for (int nn = 0; nn < H; nn++)
            acc = __fmaf_rn(sh[nn], W100[(size_t)nn*NP + tid], acc);
        s_logit[tid] = __fadd_rn(acc, b100[tid]);
    } else if (tid < NP + 2) {
        int j = tid - NP;
        float acc = 0.f;
        for (int nn = 0; nn < H; nn++)
            acc = __fmaf_rn(sh[nn], W2[nn*2 + j], acc);
        s_x2[j] = __fadd_rn(acc, b2[j]);
    }
    __syncthreads();
    if (tid == 0) {
        float mx = s_logit[0];
        for (int i = 1; i < NP; i++) mx = fmaxf(mx, s_logit[i]);
        float sum = 0.f;
        for (int i = 0; i < NP; i++) { float ev = expf(__fsub_rn(s_logit[i], mx)); s_logit[i] = ev; sum += ev; }
        const float* xb = xx + (size_t)b*NP*F_IN;
        float px = 0.f, py = 0.f, pz = 0.f, E = 0.f;
        for (int i = 0; i < NP; i++) {
            float w = __fmul_rn(__fdiv_rn(s_logit[i], sum), xb[i*F_IN + 7]);
            px = __fmaf_rn(xb[i*F_IN + 3], w, px);
            py = __fmaf_rn(xb[i*F_IN + 4], w, py);
            pz = __fmaf_rn(xb[i*F_IN + 5], w, pz);
            E  = __fmaf_rn(xb[i*F_IN + 6], w, E);
        }
        float px2 = __fmul_rn(px,px), py2 = __fmul_rn(py,py), pz2 = __fmul_rn(pz,pz);
        float pt = __fsqrt_rn(__fadd_rn(px2, py2));
        float mass2 = __fsub_rn(__fsub_rn(__fsub_rn(__fmul_rn(E,E), px2), py2), pz2);
        float absp = __fsqrt_rn(__fadd_rn(__fadd_rn(px2, py2), pz2));
        float denom = (absp == 0.f) ? 1.f : absp;
        float cosT  = (absp == 0.f) ? 1.f : __fdiv_rn(pz, denom);
        bool ok = (__fmul_rn(cosT,cosT) < 1.f);
        float ratio = ok ? __fdiv_rn(__fsub_rn(1.f, cosT), __fadd_rn(1.f, cosT)) : 1.f;
        float eta = ok ? __fmul_rn(-0.5f, logf(ratio)) : 0.f;
        float phi = (px == 0.f && py == 0.f) ? 0.f : atan2f(py, px);
        out[b*6+0] = s_x2[0];
        out[b*6+1] = s_x2[1];
        out[b*6+2] = pt;
        out[b*6+3] = eta;
        out[b*6+4] = phi;
        out[b*6+5] = mass2;
    }
}

// ---------------- launch ----------------
extern "C" void kernel_launch(void* const* d_in, const int* in_sizes, int n_in,
                              void* d_out, int out_size) {
    const float* xx    = (const float*)d_in[0];
    const float* emb1  = (const float*)d_in[1];
    const float* emb2  = (const float*)d_in[2];
    const float* emb3  = (const float*)d_in[3];
    const float* mean  = (const float*)d_in[4];
    const float* stdv  = (const float*)d_in[5];
    const float* vmin  = (const float*)d_in[6];
    const float* vmax  = (const float*)d_in[7];
    const float* W0    = (const float*)d_in[8];
    const float* b0    = (const float*)d_in[9];
    const float* Wh    = (const float*)d_in[10];
    const float* bh    = (const float*)d_in[11];
    const float* gamma = (const float*)d_in[12];
    const float* beta  = (const float*)d_in[13];
    const float* mmean = (const float*)d_in[14];
    const float* mvar  = (const float*)d_in[15];
    const float* Wc    = (const float*)d_in[16];
    const float* bc    = (const float*)d_in[17];
    const float* W2    = (const float*)d_in[18];
    const float* b2    = (const float*)d_in[19];
    const float* W100  = (const float*)d_in[20];
    const float* b100  = (const float*)d_in[21];

    float *pG, *pA, *pB;
    cudaGetSymbolAddress((void**)&pG, d_g);
    cudaGetSymbolAddress((void**)&pA, d_hA);
    cudaGetSymbolAddress((void**)&pB, d_hB);

    prep_kernel<<<(B*NP + 255)/256, 256>>>(xx, emb1, emb2, emb3, mean, stdv, vmin, vmax);

    const dim3 GL((H + 31)/32, SPLITK);     // (113, 4) -> 452 blocks (co-resident)

    for (int it = 0; it < NP; it++) {
        knn_kernel<<<B, 128>>>(Wc, bc, it > 0 ? 1 : 0);

        layer_kernel<<<GL, 256>>>(pG, GDIM, W0, b0,
                                  gamma, beta, mmean, mvar, pA);
        layer_kernel<<<GL, 256>>>(pA, H, Wh + 0*(size_t)H*H, bh + 0*H,
                                  gamma + 1*H, beta + 1*H, mmean + 1*H, mvar + 1*H, pB);
        layer_kernel<<<GL, 256>>>(pB, H, Wh + 1*(size_t)H*H, bh + 1*H,
                                  gamma + 2*H, beta + 2*H, mmean + 2*H, mvar + 2*H, pA);
        layer_kernel<<<GL, 256>>>(pA, H, Wh + 2*(size_t)H*H, bh + 2*H,
                                  gamma + 3*H, beta + 3*H, mmean + 3*H, mvar + 3*H, pB);
        layer_kernel<<<GL, 256>>>(pB, H, Wh + 3*(size_t)H*H, bh + 3*H,
                                  gamma + 4*H, beta + 4*H, mmean + 4*H, mvar + 4*H, pA);
    }

    heads_kernel<<<B, 256>>>(xx, W2, b2, W100, b100, (float*)d_out);
}